// round 8
// baseline (speedup 1.0000x reference)
#include <cuda_runtime.h>
#include <cstdint>

#define Bn 64
#define Tn 2048
#define Dn 512
#define Un 32
#define FULLM 0xffffffffu
typedef unsigned long long ull;

// ---------------- packed f32x2 ops ----------------
__device__ __forceinline__ ull fma2(ull a, ull b, ull c) {
    ull d;
    asm("fma.rn.f32x2 %0, %1, %2, %3;" : "=l"(d) : "l"(a), "l"(b), "l"(c));
    return d;
}
__device__ __forceinline__ ull add2(ull a, ull b) {
    ull d;
    asm("add.rn.f32x2 %0, %1, %2;" : "=l"(d) : "l"(a), "l"(b));
    return d;
}
__device__ __forceinline__ void unpack2(ull a, float& lo, float& hi) {
    asm("mov.b64 {%0, %1}, %2;" : "=f"(lo), "=f"(hi) : "l"(a));
}
__device__ __forceinline__ ull pack2(float lo, float hi) {
    ull d;
    asm("mov.b64 %0, {%1, %2};" : "=l"(d) : "f"(lo), "f"(hi));
    return d;
}
__device__ __forceinline__ void cp16(float* smem_ptr, const float* gptr) {
    unsigned saddr = (unsigned)__cvta_generic_to_shared(smem_ptr);
    asm volatile("cp.async.cg.shared.global [%0], [%1], 16;" :: "r"(saddr), "l"(gptr));
}

// 16 MB logits scratch
__device__ float g_logits[(size_t)Bn * Tn * Un];

// ---------------- GEMM v4: cp.async double-buffered tiles ----------------
// 1024 blocks x 512 threads. Block = 128 rows, k in 4 tiles of 128.
__global__ __launch_bounds__(512, 1) void gemm_kernel(const float* __restrict__ x,
                                                      const float* __restrict__ W,
                                                      const float* __restrict__ bias,
                                                      float* __restrict__ out) {
    extern __shared__ float smf[];
    float* sWt = smf;             // 32 * 520 = 16640 floats
    float* sx = smf + 16640;      // 2 * 128 * 128 floats

    const int tid = threadIdx.x;
    const int row0 = blockIdx.x * 128;

    // stage tile 0 (async)
    {
        const float* gsrc = x + (size_t)row0 * Dn;
#pragma unroll
        for (int q = 0; q < 8; q++) {
            int lin = tid + 512 * q;
            int rr = lin >> 5, cc = lin & 31;
            cp16(sx + rr * 128 + cc * 4, gsrc + (size_t)rr * Dn + cc * 4);
        }
        asm volatile("cp.async.commit_group;");
    }
    // W transposed into smem [u][k], pad 520
    for (int i = tid; i < Dn * Un; i += 512) {
        int k = i >> 5, u = i & 31;
        sWt[u * 520 + k] = W[i];
    }

    const int w = tid >> 5, u = tid & 31;
    const int wr0 = w * 8;

    ull acc[8];
#pragma unroll
    for (int r = 0; r < 8; r++) acc[r] = 0ull;

    for (int kt = 0; kt < 4; kt++) {
        if (kt < 3) {  // stage next tile into the other buffer
            const float* gsrc = x + (size_t)row0 * Dn + (kt + 1) * 128;
            float* sdst = sx + ((kt + 1) & 1) * 16384;
#pragma unroll
            for (int q = 0; q < 8; q++) {
                int lin = tid + 512 * q;
                int rr = lin >> 5, cc = lin & 31;
                cp16(sdst + rr * 128 + cc * 4, gsrc + (size_t)rr * Dn + cc * 4);
            }
            asm volatile("cp.async.commit_group;");
            asm volatile("cp.async.wait_group 1;");   // tile kt complete
        } else {
            asm volatile("cp.async.wait_group 0;");
        }
        __syncthreads();  // tile kt (and W on kt==0) visible block-wide

        const float* wbase = sWt + u * 520 + kt * 128;
        const float* xbuf = sx + (kt & 1) * 16384;
        for (int k8 = 0; k8 < 128; k8 += 8) {
            ulonglong2 w0 = *(const ulonglong2*)(wbase + k8);
            ulonglong2 w1 = *(const ulonglong2*)(wbase + k8 + 4);
#pragma unroll
            for (int r = 0; r < 8; r++) {
                const float* xr = xbuf + (wr0 + r) * 128 + k8;
                ulonglong2 x0 = *(const ulonglong2*)(xr);
                ulonglong2 x1 = *(const ulonglong2*)(xr + 4);
                acc[r] = fma2(x0.x, w0.x, acc[r]);
                acc[r] = fma2(x0.y, w0.y, acc[r]);
                acc[r] = fma2(x1.x, w1.x, acc[r]);
                acc[r] = fma2(x1.y, w1.y, acc[r]);
            }
        }
        __syncthreads();  // compute(kt) done before buffer reuse
    }

    float bu = bias[u];
#pragma unroll
    for (int r = 0; r < 8; r++) {
        float lo, hi;
        unpack2(acc[r], lo, hi);
        out[(size_t)(row0 + wr0 + r) * Un + u] = lo + hi + bu;
    }
}

// ---------------- Viterbi v4: 64 threads, 2-way split, no in-loop comp ----------------
// tid: j = tid>>1 (target tag), sub = tid&1 (i-range sub*16..sub*16+15)
__device__ __forceinline__ float ldclamp(const float* lg, int t, int tmax, int j) {
    int ti = t <= tmax ? t : tmax;
    return lg[ti * Un + j];
}

__device__ __forceinline__ void vstep(int t, float lgt, const ull* tcp, float* abuf,
                                      unsigned char* bp, int j, int sub) {
    __syncthreads();  // previous step's abuf store visible
    const ulonglong2* ap = (const ulonglong2*)(abuf + ((t - 1) & 1) * 32 + sub * 16);
    ulonglong2 a0 = ap[0];
    ulonglong2 a1 = ap[1];
    ulonglong2 a2 = ap[2];
    ulonglong2 a3 = ap[3];
    ull s0 = add2(a0.x, tcp[0]), s1 = add2(a0.y, tcp[1]);
    ull s2 = add2(a1.x, tcp[2]), s3 = add2(a1.y, tcp[3]);
    ull s4 = add2(a2.x, tcp[4]), s5 = add2(a2.y, tcp[5]);
    ull s6 = add2(a3.x, tcp[6]), s7 = add2(a3.y, tcp[7]);
    float v0, v1, v2, v3, v4, v5, v6, v7, v8, v9, va, vb, vc, vd, ve, vf;
    unpack2(s0, v0, v1); unpack2(s1, v2, v3);
    unpack2(s2, v4, v5); unpack2(s3, v6, v7);
    unpack2(s4, v8, v9); unpack2(s5, va, vb);
    unpack2(s6, vc, vd); unpack2(s7, ve, vf);
    const int ib = sub * 16;
    // 16 -> 1, strict '>' so lower index wins ties (matches jnp.argmax)
    bool g0 = v1 > v0; float m0 = fmaxf(v0, v1); int i0 = g0 ? ib + 1 : ib;
    bool g1 = v3 > v2; float m1 = fmaxf(v2, v3); int i1 = g1 ? ib + 3 : ib + 2;
    bool g2 = v5 > v4; float m2 = fmaxf(v4, v5); int i2 = g2 ? ib + 5 : ib + 4;
    bool g3 = v7 > v6; float m3 = fmaxf(v6, v7); int i3 = g3 ? ib + 7 : ib + 6;
    bool g4 = v9 > v8; float m4 = fmaxf(v8, v9); int i4 = g4 ? ib + 9 : ib + 8;
    bool g5 = vb > va; float m5 = fmaxf(va, vb); int i5 = g5 ? ib + 11 : ib + 10;
    bool g6 = vd > vc; float m6 = fmaxf(vc, vd); int i6 = g6 ? ib + 13 : ib + 12;
    bool g7 = vf > ve; float m7 = fmaxf(ve, vf); int i7 = g7 ? ib + 15 : ib + 14;
    bool h0 = m1 > m0; float n0 = fmaxf(m0, m1); int k0 = h0 ? i1 : i0;
    bool h1 = m3 > m2; float n1 = fmaxf(m2, m3); int k1 = h1 ? i3 : i2;
    bool h2 = m5 > m4; float n2 = fmaxf(m4, m5); int k2 = h2 ? i5 : i4;
    bool h3 = m7 > m6; float n3 = fmaxf(m6, m7); int k3 = h3 ? i7 : i6;
    bool p0 = n1 > n0; float q0 = fmaxf(n0, n1); int l0 = p0 ? k1 : k0;
    bool p1 = n3 > n2; float q1 = fmaxf(n2, n3); int l1 = p1 ? k3 : k2;
    bool pf = q1 > q0; float val = fmaxf(q0, q1); int idx = pf ? l1 : l0;
    val += lgt;  // commutes with max; off the post-merge chain
    // single pair merge (sub ranges ordered, so (pv==val && pi<idx) keeps first occurrence)
    float pv = __shfl_xor_sync(FULLM, val, 1);
    int pi = __shfl_xor_sync(FULLM, idx, 1);
    bool take = (pv > val) || (pv == val && pi < idx);
    val = take ? pv : val;
    idx = take ? pi : idx;
    if (sub == 0) abuf[(t & 1) * 32 + j] = val;
    else bp[t * 32 + j] = (unsigned char)idx;
}

__global__ __launch_bounds__(64, 1) void viterbi_kernel(const float* __restrict__ logits,
                                                        const int* __restrict__ nwords,
                                                        const float* __restrict__ trans,
                                                        float* __restrict__ out,
                                                        int write_pred, int write_score,
                                                        long long score_off) {
    extern __shared__ unsigned char sm[];
    unsigned char* bp = sm;                            // 65536
    unsigned char* pmap = sm + 65536;                  // 1024 (32 chunks x 32 origins)
    int* anch = (int*)(sm + 65536 + 1024);             // 128
    float* abuf = (float*)(sm + 65536 + 1024 + 128);   // 256 (2 x 32)
    int* sfin = (int*)(sm + 65536 + 1024 + 128 + 256); // 8

    const int tid = threadIdx.x;
    const int j = tid >> 1;
    const int sub = tid & 1;
    const int b = blockIdx.x;
    int len = nwords[b];
    if (len < 1) len = 1;
    if (len > Tn) len = Tn;
    const int tmax = len - 1;

    const float* lg = logits + (size_t)b * Tn * Un;

    // my 16 trans rows for column j, packed in pairs
    ull tcp[8];
#pragma unroll
    for (int p = 0; p < 8; p++)
        tcp[p] = pack2(trans[(sub * 16 + 2 * p) * Un + j],
                       trans[(sub * 16 + 2 * p + 1) * Un + j]);

    if (tid < 32) abuf[tid] = lg[tid];  // alpha0
    __syncthreads();

    // 4-deep rotating logit prefetch
    float pl0 = ldclamp(lg, 1, tmax, j);
    float pl1 = ldclamp(lg, 2, tmax, j);
    float pl2 = ldclamp(lg, 3, tmax, j);
    float pl3 = ldclamp(lg, 4, tmax, j);

    int t = 1;
    for (; t + 3 <= tmax; t += 4) {
        float n0 = ldclamp(lg, t + 4, tmax, j);
        float n1 = ldclamp(lg, t + 5, tmax, j);
        float n2 = ldclamp(lg, t + 6, tmax, j);
        float n3 = ldclamp(lg, t + 7, tmax, j);
        vstep(t, pl0, tcp, abuf, bp, j, sub);
        vstep(t + 1, pl1, tcp, abuf, bp, j, sub);
        vstep(t + 2, pl2, tcp, abuf, bp, j, sub);
        vstep(t + 3, pl3, tcp, abuf, bp, j, sub);
        pl0 = n0; pl1 = n1; pl2 = n2; pl3 = n3;
    }
    for (; t <= tmax; t++) {
        vstep(t, pl0, tcp, abuf, bp, j, sub);
        pl0 = pl1; pl1 = pl2; pl2 = pl3;
    }
    __syncthreads();

    const int fslot = (tmax & 1) * 32;
    // warp 0: argmax over final alpha, lowest-index tie-break
    if (tid < 32) {
        float bv = abuf[fslot + tid];
        int bi = tid;
#pragma unroll
        for (int off = 16; off >= 1; off >>= 1) {
            float ov = __shfl_xor_sync(FULLM, bv, off);
            int oi = __shfl_xor_sync(FULLM, bi, off);
            if (ov > bv || (ov == bv && oi < bi)) { bv = ov; bi = oi; }
        }
        if (tid == 0) {
            sfin[0] = bi;
            if (write_score) out[score_off + b] = bv;
        }
    }

    if (write_pred) {
        // build per-chunk backward maps: pmap[c][e] = tag@(c*64) given tag e@min((c+1)*64,tmax)
        int tg[16];
        int cc_[16], thi_[16];
#pragma unroll
        for (int r = 0; r < 16; r++) {
            int p = tid + 64 * r;
            int c = p >> 5;
            tg[r] = p & 31;
            int th = (c + 1) << 6;
            if (th > tmax) th = tmax;
            cc_[r] = c << 6;
            thi_[r] = th;
        }
        for (int s = 0; s < 64; s++) {
#pragma unroll
            for (int r = 0; r < 16; r++) {
                int tt = thi_[r] - s;
                if (tt > cc_[r]) tg[r] = bp[tt * 32 + tg[r]];
            }
        }
#pragma unroll
        for (int r = 0; r < 16; r++) {
            int p = tid + 64 * r;
            pmap[(p >> 5) * 32 + (p & 31)] = (unsigned char)tg[r];
        }
        __syncthreads();

        const int last_tag = sfin[0];
        const int cmax = tmax >> 6;
        if (tid == 0) {
            int a = last_tag;
            for (int c = cmax; c >= 0; --c) {
                a = pmap[c * 32 + a];
                anch[c] = a;  // tag @ c*64
            }
        }
        // tail: pred[t] = last_tag for t >= tmax
        for (int tt = tmax + tid; tt < Tn; tt += 64)
            out[(size_t)b * Tn + tt] = (float)last_tag;
        __syncthreads();

        // parallel per-chunk backtrack (thread c handles t in (c*64, t_hi])
        if (tid <= cmax) {
            int thi = (tid == cmax) ? tmax : ((tid + 1) << 6);
            int tg2 = (tid == cmax) ? last_tag : anch[tid + 1];
            for (int tt = thi; tt > (tid << 6); --tt) {
                tg2 = bp[tt * 32 + tg2];
                out[(size_t)b * Tn + tt - 1] = (float)tg2;
            }
        }
    }
}

// ---------------- launch ----------------
extern "C" void kernel_launch(void* const* d_in, const int* in_sizes, int n_in,
                              void* d_out, int out_size) {
    const float* x = (const float*)d_in[0];
    const int* nwords = (const int*)d_in[1];
    const float* W = (const float*)d_in[2];
    const float* trans = (const float*)d_in[3];
    const float* bias = (const float*)d_in[4];
    float* out = (float*)d_out;

    const int BT = Bn * Tn;
    int write_pred = 1, write_score = 0;
    long long score_off = BT;
    if (out_size >= BT + Bn) {
        write_score = 1;
    } else if (out_size == Bn) {  // scores only
        write_pred = 0;
        write_score = 1;
        score_off = 0;
    }

    static float* logits_ptr = nullptr;
    if (!logits_ptr) cudaGetSymbolAddress((void**)&logits_ptr, g_logits);

    const int gemm_smem = (16640 + 2 * 16384) * 4;       // 197632
    const int vit_smem = 65536 + 1024 + 128 + 256 + 8;   // 66952
    cudaFuncSetAttribute(gemm_kernel, cudaFuncAttributeMaxDynamicSharedMemorySize, gemm_smem);
    cudaFuncSetAttribute(viterbi_kernel, cudaFuncAttributeMaxDynamicSharedMemorySize, vit_smem);

    gemm_kernel<<<(Bn * Tn) / 128, 512, gemm_smem>>>(x, W, bias, logits_ptr);
    viterbi_kernel<<<Bn, 64, vit_smem>>>(logits_ptr, nwords, trans, out,
                                         write_pred, write_score, score_off);
}

// round 9
// speedup vs baseline: 1.2190x; 1.2190x over previous
#include <cuda_runtime.h>
#include <cstdint>

#define Bn 64
#define Tn 2048
#define Dn 512
#define Un 32
#define FULLM 0xffffffffu
typedef unsigned long long ull;

// ---------------- packed f32x2 ops ----------------
__device__ __forceinline__ ull fma2(ull a, ull b, ull c) {
    ull d;
    asm("fma.rn.f32x2 %0, %1, %2, %3;" : "=l"(d) : "l"(a), "l"(b), "l"(c));
    return d;
}
__device__ __forceinline__ ull add2(ull a, ull b) {
    ull d;
    asm("add.rn.f32x2 %0, %1, %2;" : "=l"(d) : "l"(a), "l"(b));
    return d;
}
__device__ __forceinline__ void unpack2(ull a, float& lo, float& hi) {
    asm("mov.b64 {%0, %1}, %2;" : "=f"(lo), "=f"(hi) : "l"(a));
}
__device__ __forceinline__ ull pack2(float lo, float hi) {
    ull d;
    asm("mov.b64 %0, {%1, %2};" : "=l"(d) : "f"(lo), "f"(hi));
    return d;
}
__device__ __forceinline__ void cp16(float* smem_ptr, const float* gptr) {
    unsigned saddr = (unsigned)__cvta_generic_to_shared(smem_ptr);
    asm volatile("cp.async.cg.shared.global [%0], [%1], 16;" :: "r"(saddr), "l"(gptr));
}

// scratch: 16 MB logits + ready flags (b,c): c = 64-step chunk, 32 per batch
__device__ float g_logits[(size_t)Bn * Tn * Un];
__device__ int g_flags[Bn * 32];

#define NCHUNK 32
#define GEMM_BLOCKS (NCHUNK * Bn)   // 2048, 64 rows each
#define SMEM_BYTES 67208            // max(viterbi 67208, gemm 65536)

// ================= GEMM role: 64 rows (one 64-step chunk of one batch) ==========
__device__ void gemm_role(int c, int b, const float* __restrict__ x,
                          const float* __restrict__ W,
                          const float* __restrict__ bias, char* smem) {
    float* sx = (float*)smem;  // 2 x 64 x 128 floats (64KB)
    const int tid = threadIdx.x;
    const size_t row0 = (size_t)b * Tn + c * 64;  // global logit row

    // stage tile 0 (k in [0,128))
    {
        const float* gsrc = x + row0 * Dn;
#pragma unroll
        for (int q = 0; q < 16; q++) {
            int lin = tid + 128 * q;
            int rr = lin >> 5, cc = lin & 31;
            cp16(sx + rr * 128 + cc * 4, gsrc + (size_t)rr * Dn + cc * 4);
        }
        asm volatile("cp.async.commit_group;");
    }

    const int w = tid >> 5, u = tid & 31;
    const int wr0 = w * 16;

    ull acc[16];
#pragma unroll
    for (int r = 0; r < 16; r++) acc[r] = 0ull;

    for (int kt = 0; kt < 4; kt++) {
        if (kt < 3) {
            const float* gsrc = x + row0 * Dn + (kt + 1) * 128;
            float* sdst = sx + ((kt + 1) & 1) * 8192;
#pragma unroll
            for (int q = 0; q < 16; q++) {
                int lin = tid + 128 * q;
                int rr = lin >> 5, cc = lin & 31;
                cp16(sdst + rr * 128 + cc * 4, gsrc + (size_t)rr * Dn + cc * 4);
            }
            asm volatile("cp.async.commit_group;");
            asm volatile("cp.async.wait_group 1;");
        } else {
            asm volatile("cp.async.wait_group 0;");
        }
        __syncthreads();

        const float* xbuf = sx + (kt & 1) * 8192;
        const float* wg = W + (kt * 128) * Un + u;
        for (int k8 = 0; k8 < 128; k8 += 8) {
            // W from L1 (64KB, stays resident): 8 coalesced scalar loads
            float wv0 = __ldg(wg + (k8 + 0) * Un);
            float wv1 = __ldg(wg + (k8 + 1) * Un);
            float wv2 = __ldg(wg + (k8 + 2) * Un);
            float wv3 = __ldg(wg + (k8 + 3) * Un);
            float wv4 = __ldg(wg + (k8 + 4) * Un);
            float wv5 = __ldg(wg + (k8 + 5) * Un);
            float wv6 = __ldg(wg + (k8 + 6) * Un);
            float wv7 = __ldg(wg + (k8 + 7) * Un);
            ull wp0 = pack2(wv0, wv1), wp1 = pack2(wv2, wv3);
            ull wp2 = pack2(wv4, wv5), wp3 = pack2(wv6, wv7);
#pragma unroll
            for (int r = 0; r < 16; r++) {
                const float* xr = xbuf + (wr0 + r) * 128 + k8;
                ulonglong2 x0 = *(const ulonglong2*)(xr);
                ulonglong2 x1 = *(const ulonglong2*)(xr + 4);
                acc[r] = fma2(x0.x, wp0, acc[r]);
                acc[r] = fma2(x0.y, wp1, acc[r]);
                acc[r] = fma2(x1.x, wp2, acc[r]);
                acc[r] = fma2(x1.y, wp3, acc[r]);
            }
        }
        __syncthreads();
    }

    float bu = bias[u];
#pragma unroll
    for (int r = 0; r < 16; r++) {
        float lo, hi;
        unpack2(acc[r], lo, hi);
        g_logits[(row0 + wr0 + r) * Un + u] = lo + hi + bu;
    }
    __syncthreads();        // all STGs program-ordered before fence
    if (tid == 0) {
        __threadfence();    // logits visible gpu-wide before flag
        atomicExch(&g_flags[b * NCHUNK + c], 1);
    }
}

// ================= Viterbi role (R6 design + chunk gates) ======================
// tid: j = tid>>2 (target tag), sub = tid&3 (i-range sub*8..sub*8+7)
__device__ __forceinline__ float ldclamp(const float* lg, int t, int tmax, int j) {
    int ti = t <= tmax ? t : tmax;
    return lg[ti * Un + j];
}

__device__ __forceinline__ void vstep(int t, float lgt, const ull* tcp, float* abuf,
                                      int* cbuf, unsigned char* bp, unsigned char* chk,
                                      int j, int sub) {
    __syncthreads();  // previous step's abuf/cbuf stores visible
    const ulonglong2* ap = (const ulonglong2*)(abuf + ((t - 1) & 1) * 32 + sub * 8);
    ulonglong2 a0 = ap[0];
    ulonglong2 a1 = ap[1];
    ull s0 = add2(a0.x, tcp[0]);
    ull s1 = add2(a0.y, tcp[1]);
    ull s2 = add2(a1.x, tcp[2]);
    ull s3 = add2(a1.y, tcp[3]);
    float v0, v1, v2, v3, v4, v5, v6, v7;
    unpack2(s0, v0, v1);
    unpack2(s1, v2, v3);
    unpack2(s2, v4, v5);
    unpack2(s3, v6, v7);
    const int ib = sub * 8;
    // 8 -> 1, strict '>' so lower index wins ties (matches jnp.argmax)
    bool gA = v1 > v0; float m01 = fmaxf(v0, v1); int i01 = gA ? ib + 1 : ib;
    bool gB = v3 > v2; float m23 = fmaxf(v2, v3); int i23 = gB ? ib + 3 : ib + 2;
    bool gC = v5 > v4; float m45 = fmaxf(v4, v5); int i45 = gC ? ib + 5 : ib + 4;
    bool gD = v7 > v6; float m67 = fmaxf(v6, v7); int i67 = gD ? ib + 7 : ib + 6;
    bool gE = m23 > m01; float mA = fmaxf(m01, m23); int iA = gE ? i23 : i01;
    bool gF = m67 > m45; float mB = fmaxf(m45, m67); int iB = gF ? i67 : i45;
    bool gG = mB > mA; float val = fmaxf(mA, mB); int idx = gG ? iB : iA;
    // quad merge (sub ranges ordered by sub -> first-occurrence preserved)
#pragma unroll
    for (int d = 1; d <= 2; d <<= 1) {
        float pv = __shfl_xor_sync(FULLM, val, d);
        int pi = __shfl_xor_sync(FULLM, idx, d);
        bool take = (pv > val) || (pv == val && pi < idx);
        val = take ? pv : val;
        idx = take ? pi : idx;
    }
    if (sub == 0) {
        abuf[(t & 1) * 32 + j] = val + lgt;
        bp[t * 32 + j] = (unsigned char)idx;
        int pc = cbuf[((t - 1) & 1) * 32 + idx];
        if ((t & 63) == 0) {
            chk[(t >> 6) * 32 + j] = (unsigned char)pc;
            pc = j;
        }
        cbuf[(t & 1) * 32 + j] = pc;
    }
}

__device__ __forceinline__ void waitchunk(int b, int c) {
    if (c > NCHUNK - 1) c = NCHUNK - 1;
    volatile int* f = &g_flags[b * NCHUNK + c];
    while (*f == 0) {}
    __threadfence();  // acquire: logits for this chunk visible
}

__device__ void viterbi_role(int b, const float* __restrict__ trans,
                             float* __restrict__ out, int write_pred, int write_score,
                             long long score_off, const int* __restrict__ nwords,
                             char* smbase) {
    unsigned char* bp = (unsigned char*)smbase;            // 65536
    unsigned char* chk = (unsigned char*)smbase + 65536;   // 1024
    int* anch = (int*)(smbase + 65536 + 1024);             // 128
    float* abuf = (float*)(smbase + 65536 + 1024 + 128);   // 256
    int* cbuf = (int*)(smbase + 65536 + 1024 + 128 + 256); // 256
    int* sfin = (int*)(smbase + 65536 + 1024 + 128 + 512); // 8

    const int tid = threadIdx.x;
    const int j = tid >> 2;
    const int sub = tid & 3;
    int len = nwords[b];
    if (len < 1) len = 1;
    if (len > Tn) len = Tn;
    const int tmax = len - 1;

    const float* lg = g_logits + (size_t)b * Tn * Un;

    ull tcp[4];
#pragma unroll
    for (int p = 0; p < 4; p++)
        tcp[p] = pack2(trans[(sub * 8 + 2 * p) * Un + j],
                       trans[(sub * 8 + 2 * p + 1) * Un + j]);

    waitchunk(b, 0);
    if (tid < 32) {
        abuf[tid] = lg[tid];  // alpha0
        cbuf[tid] = tid;
    }
    __syncthreads();

    // 4-deep rotating logit prefetch
    float pl0 = ldclamp(lg, 1, tmax, j);
    float pl1 = ldclamp(lg, 2, tmax, j);
    float pl2 = ldclamp(lg, 3, tmax, j);
    float pl3 = ldclamp(lg, 4, tmax, j);

    int t = 1;
    for (; t + 3 <= tmax; t += 4) {
        if ((t & 63) == 1) waitchunk(b, (t >> 6) + 1);  // next chunk (prefetch reach)
        float n0 = ldclamp(lg, t + 4, tmax, j);
        float n1 = ldclamp(lg, t + 5, tmax, j);
        float n2 = ldclamp(lg, t + 6, tmax, j);
        float n3 = ldclamp(lg, t + 7, tmax, j);
        vstep(t, pl0, tcp, abuf, cbuf, bp, chk, j, sub);
        vstep(t + 1, pl1, tcp, abuf, cbuf, bp, chk, j, sub);
        vstep(t + 2, pl2, tcp, abuf, cbuf, bp, chk, j, sub);
        vstep(t + 3, pl3, tcp, abuf, cbuf, bp, chk, j, sub);
        pl0 = n0; pl1 = n1; pl2 = n2; pl3 = n3;
    }
    for (; t <= tmax; t++) {
        if ((t & 63) == 1) waitchunk(b, (t >> 6) + 1);
        vstep(t, pl0, tcp, abuf, cbuf, bp, chk, j, sub);
        pl0 = pl1; pl1 = pl2; pl2 = pl3;
    }
    __syncthreads();

    const int fslot = (tmax & 1) * 32;
    if (tid < 32) {
        float bv = abuf[fslot + tid];
        int bi = tid;
#pragma unroll
        for (int off = 16; off >= 1; off >>= 1) {
            float ov = __shfl_xor_sync(FULLM, bv, off);
            int oi = __shfl_xor_sync(FULLM, bi, off);
            if (ov > bv || (ov == bv && oi < bi)) { bv = ov; bi = oi; }
        }
        if (tid == 0) {
            sfin[0] = bi;
            if (write_score) out[score_off + b] = bv;
        }
    }
    __syncthreads();
    const int last_tag = sfin[0];

    if (write_pred) {
        const int nA = tmax >> 6;
        if (tid == 0) {
            anch[nA] = cbuf[fslot + last_tag];
            for (int cI = nA; cI >= 1; --cI) anch[cI - 1] = chk[cI * 32 + anch[cI]];
        }
        for (int tt = tmax + tid; tt < Tn; tt += 128)
            out[(size_t)b * Tn + tt] = (float)last_tag;
        __syncthreads();

        if (tid <= nA) {
            int thi = (tid == nA) ? tmax : ((tid + 1) << 6);
            int tg = (tid == nA) ? last_tag : anch[tid + 1];
            for (int tt = thi; tt > (tid << 6); --tt) {
                tg = bp[tt * 32 + tg];
                out[(size_t)b * Tn + tt - 1] = (float)tg;
            }
        }
    }
}

// ================= fused kernel ======================
__global__ __launch_bounds__(128, 3) void crf_fused(const float* __restrict__ x,
                                                    const int* __restrict__ nwords,
                                                    const float* __restrict__ W,
                                                    const float* __restrict__ trans,
                                                    const float* __restrict__ bias,
                                                    float* __restrict__ out,
                                                    int write_pred, int write_score,
                                                    long long score_off) {
    extern __shared__ char smem[];
    int g = blockIdx.x;
    if (g < Bn) {
        viterbi_role(g, trans, out, write_pred, write_score, score_off, nwords, smem);
    } else {
        int gg = g - Bn;
        gemm_role(gg >> 6, gg & 63, x, W, bias, smem);
    }
}

// ---------------- launch ----------------
extern "C" void kernel_launch(void* const* d_in, const int* in_sizes, int n_in,
                              void* d_out, int out_size) {
    const float* x = (const float*)d_in[0];
    const int* nwords = (const int*)d_in[1];
    const float* W = (const float*)d_in[2];
    const float* trans = (const float*)d_in[3];
    const float* bias = (const float*)d_in[4];
    float* out = (float*)d_out;

    const int BT = Bn * Tn;
    int write_pred = 1, write_score = 0;
    long long score_off = BT;
    if (out_size >= BT + Bn) {
        write_score = 1;
    } else if (out_size == Bn) {
        write_pred = 0;
        write_score = 1;
        score_off = 0;
    }

    static int* flags_ptr = nullptr;
    if (!flags_ptr) cudaGetSymbolAddress((void**)&flags_ptr, g_flags);

    cudaFuncSetAttribute(crf_fused, cudaFuncAttributeMaxDynamicSharedMemorySize, SMEM_BYTES);

    cudaMemsetAsync(flags_ptr, 0, Bn * NCHUNK * sizeof(int));
    crf_fused<<<Bn + GEMM_BLOCKS, 128, SMEM_BYTES>>>(x, nwords, W, trans, bias, out,
                                                     write_pred, write_score, score_off);
}

// round 10
// speedup vs baseline: 1.4100x; 1.1566x over previous
#include <cuda_runtime.h>
#include <cstdint>

#define Bn 64
#define Tn 2048
#define Dn 512
#define Un 32
#define FULLM 0xffffffffu
typedef unsigned long long ull;

// ---------------- packed f32x2 ops ----------------
__device__ __forceinline__ ull fma2(ull a, ull b, ull c) {
    ull d;
    asm("fma.rn.f32x2 %0, %1, %2, %3;" : "=l"(d) : "l"(a), "l"(b), "l"(c));
    return d;
}
__device__ __forceinline__ ull add2(ull a, ull b) {
    ull d;
    asm("add.rn.f32x2 %0, %1, %2;" : "=l"(d) : "l"(a), "l"(b));
    return d;
}
__device__ __forceinline__ void unpack2(ull a, float& lo, float& hi) {
    asm("mov.b64 {%0, %1}, %2;" : "=f"(lo), "=f"(hi) : "l"(a));
}
__device__ __forceinline__ ull pack2(float lo, float hi) {
    ull d;
    asm("mov.b64 %0, {%1, %2};" : "=l"(d) : "f"(lo), "f"(hi));
    return d;
}
__device__ __forceinline__ void cp16(float* smem_ptr, const float* gptr) {
    unsigned saddr = (unsigned)__cvta_generic_to_shared(smem_ptr);
    asm volatile("cp.async.cg.shared.global [%0], [%1], 16;" :: "r"(saddr), "l"(gptr));
}

#define NCHUNK 32
#define NJOBS (NCHUNK * Bn)        // 2048 gemm chunk-jobs
#define NBLOCKS 456                // 152 SMs x occ3
#define SMEM_BYTES 67208

// scratch: 16 MB logits + control block (flags | roles | counters), one memset
__device__ float g_logits[(size_t)Bn * Tn * Un];
// layout: [0,2048) chunk flags (b*32+c); [2048,2304) sm role; [2304] vit ctr; [2305] job ctr
__device__ int g_ctrl[2048 + 256 + 2];

// ================= GEMM job: 64 rows (one 64-step chunk of one batch) ==========
__device__ void gemm_role(int c, int b, const float* __restrict__ x,
                          const float* __restrict__ W,
                          const float* __restrict__ bias, char* smem) {
    float* sx = (float*)smem;  // 2 x 64 x 128 floats (64KB)
    const int tid = threadIdx.x;
    const size_t row0 = (size_t)b * Tn + c * 64;  // global logit row

    // stage tile 0 (k in [0,128))
    {
        const float* gsrc = x + row0 * Dn;
#pragma unroll
        for (int q = 0; q < 16; q++) {
            int lin = tid + 128 * q;
            int rr = lin >> 5, cc = lin & 31;
            cp16(sx + rr * 128 + cc * 4, gsrc + (size_t)rr * Dn + cc * 4);
        }
        asm volatile("cp.async.commit_group;");
    }

    const int w = tid >> 5, u = tid & 31;
    const int wr0 = w * 16;

    ull acc[16];
#pragma unroll
    for (int r = 0; r < 16; r++) acc[r] = 0ull;

    for (int kt = 0; kt < 4; kt++) {
        if (kt < 3) {
            const float* gsrc = x + row0 * Dn + (kt + 1) * 128;
            float* sdst = sx + ((kt + 1) & 1) * 8192;
#pragma unroll
            for (int q = 0; q < 16; q++) {
                int lin = tid + 128 * q;
                int rr = lin >> 5, cc = lin & 31;
                cp16(sdst + rr * 128 + cc * 4, gsrc + (size_t)rr * Dn + cc * 4);
            }
            asm volatile("cp.async.commit_group;");
            asm volatile("cp.async.wait_group 1;");
        } else {
            asm volatile("cp.async.wait_group 0;");
        }
        __syncthreads();

        const float* xbuf = sx + (kt & 1) * 8192;
        const float* wg = W + (kt * 128) * Un + u;
        for (int k8 = 0; k8 < 128; k8 += 8) {
            float wv0 = __ldg(wg + (k8 + 0) * Un);
            float wv1 = __ldg(wg + (k8 + 1) * Un);
            float wv2 = __ldg(wg + (k8 + 2) * Un);
            float wv3 = __ldg(wg + (k8 + 3) * Un);
            float wv4 = __ldg(wg + (k8 + 4) * Un);
            float wv5 = __ldg(wg + (k8 + 5) * Un);
            float wv6 = __ldg(wg + (k8 + 6) * Un);
            float wv7 = __ldg(wg + (k8 + 7) * Un);
            ull wp0 = pack2(wv0, wv1), wp1 = pack2(wv2, wv3);
            ull wp2 = pack2(wv4, wv5), wp3 = pack2(wv6, wv7);
#pragma unroll
            for (int r = 0; r < 16; r++) {
                const float* xr = xbuf + (wr0 + r) * 128 + k8;
                ulonglong2 x0 = *(const ulonglong2*)(xr);
                ulonglong2 x1 = *(const ulonglong2*)(xr + 4);
                acc[r] = fma2(x0.x, wp0, acc[r]);
                acc[r] = fma2(x0.y, wp1, acc[r]);
                acc[r] = fma2(x1.x, wp2, acc[r]);
                acc[r] = fma2(x1.y, wp3, acc[r]);
            }
        }
        __syncthreads();
    }

    float bu = bias[u];
#pragma unroll
    for (int r = 0; r < 16; r++) {
        float lo, hi;
        unpack2(acc[r], lo, hi);
        g_logits[(row0 + wr0 + r) * Un + u] = lo + hi + bu;
    }
    __syncthreads();        // all STGs program-ordered before fence
    if (tid == 0) {
        __threadfence();    // logits visible gpu-wide before flag
        atomicExch(&g_ctrl[b * NCHUNK + c], 1);
    }
}

// ================= Viterbi role (R6 design + chunk gates) ======================
// tid: j = tid>>2 (target tag), sub = tid&3 (i-range sub*8..sub*8+7)
__device__ __forceinline__ float ldclamp(const float* lg, int t, int tmax, int j) {
    int ti = t <= tmax ? t : tmax;
    return lg[ti * Un + j];
}

__device__ __forceinline__ void vstep(int t, float lgt, const ull* tcp, float* abuf,
                                      int* cbuf, unsigned char* bp, unsigned char* chk,
                                      int j, int sub) {
    __syncthreads();  // previous step's abuf/cbuf stores visible
    const ulonglong2* ap = (const ulonglong2*)(abuf + ((t - 1) & 1) * 32 + sub * 8);
    ulonglong2 a0 = ap[0];
    ulonglong2 a1 = ap[1];
    ull s0 = add2(a0.x, tcp[0]);
    ull s1 = add2(a0.y, tcp[1]);
    ull s2 = add2(a1.x, tcp[2]);
    ull s3 = add2(a1.y, tcp[3]);
    float v0, v1, v2, v3, v4, v5, v6, v7;
    unpack2(s0, v0, v1);
    unpack2(s1, v2, v3);
    unpack2(s2, v4, v5);
    unpack2(s3, v6, v7);
    const int ib = sub * 8;
    // 8 -> 1, strict '>' so lower index wins ties (matches jnp.argmax)
    bool gA = v1 > v0; float m01 = fmaxf(v0, v1); int i01 = gA ? ib + 1 : ib;
    bool gB = v3 > v2; float m23 = fmaxf(v2, v3); int i23 = gB ? ib + 3 : ib + 2;
    bool gC = v5 > v4; float m45 = fmaxf(v4, v5); int i45 = gC ? ib + 5 : ib + 4;
    bool gD = v7 > v6; float m67 = fmaxf(v6, v7); int i67 = gD ? ib + 7 : ib + 6;
    bool gE = m23 > m01; float mA = fmaxf(m01, m23); int iA = gE ? i23 : i01;
    bool gF = m67 > m45; float mB = fmaxf(m45, m67); int iB = gF ? i67 : i45;
    bool gG = mB > mA; float val = fmaxf(mA, mB); int idx = gG ? iB : iA;
    // quad merge (sub ranges ordered by sub -> first-occurrence preserved)
#pragma unroll
    for (int d = 1; d <= 2; d <<= 1) {
        float pv = __shfl_xor_sync(FULLM, val, d);
        int pi = __shfl_xor_sync(FULLM, idx, d);
        bool take = (pv > val) || (pv == val && pi < idx);
        val = take ? pv : val;
        idx = take ? pi : idx;
    }
    if (sub == 0) {
        abuf[(t & 1) * 32 + j] = val + lgt;
        bp[t * 32 + j] = (unsigned char)idx;
        int pc = cbuf[((t - 1) & 1) * 32 + idx];
        if ((t & 63) == 0) {
            chk[(t >> 6) * 32 + j] = (unsigned char)pc;
            pc = j;
        }
        cbuf[(t & 1) * 32 + j] = pc;
    }
}

__device__ __forceinline__ void waitchunk(int b, int c) {
    if (c > NCHUNK - 1) c = NCHUNK - 1;
    volatile int* f = &g_ctrl[b * NCHUNK + c];
    while (*f == 0) {}
    __threadfence();  // acquire: logits for this chunk visible
}

__device__ void viterbi_role(int b, const float* __restrict__ trans,
                             float* __restrict__ out, int write_pred, int write_score,
                             long long score_off, const int* __restrict__ nwords,
                             char* smbase) {
    unsigned char* bp = (unsigned char*)smbase;            // 65536
    unsigned char* chk = (unsigned char*)smbase + 65536;   // 1024
    int* anch = (int*)(smbase + 65536 + 1024);             // 128
    float* abuf = (float*)(smbase + 65536 + 1024 + 128);   // 256
    int* cbuf = (int*)(smbase + 65536 + 1024 + 128 + 256); // 256
    int* sfin = (int*)(smbase + 65536 + 1024 + 128 + 512); // 8

    const int tid = threadIdx.x;
    const int j = tid >> 2;
    const int sub = tid & 3;
    int len = nwords[b];
    if (len < 1) len = 1;
    if (len > Tn) len = Tn;
    const int tmax = len - 1;

    const float* lg = g_logits + (size_t)b * Tn * Un;

    ull tcp[4];
#pragma unroll
    for (int p = 0; p < 4; p++)
        tcp[p] = pack2(trans[(sub * 8 + 2 * p) * Un + j],
                       trans[(sub * 8 + 2 * p + 1) * Un + j]);

    waitchunk(b, 0);
    if (tid < 32) {
        abuf[tid] = lg[tid];  // alpha0
        cbuf[tid] = tid;
    }
    __syncthreads();

    // 4-deep rotating logit prefetch
    float pl0 = ldclamp(lg, 1, tmax, j);
    float pl1 = ldclamp(lg, 2, tmax, j);
    float pl2 = ldclamp(lg, 3, tmax, j);
    float pl3 = ldclamp(lg, 4, tmax, j);

    int t = 1;
    for (; t + 3 <= tmax; t += 4) {
        if ((t & 63) == 1) waitchunk(b, (t >> 6) + 1);  // next chunk (prefetch reach)
        float n0 = ldclamp(lg, t + 4, tmax, j);
        float n1 = ldclamp(lg, t + 5, tmax, j);
        float n2 = ldclamp(lg, t + 6, tmax, j);
        float n3 = ldclamp(lg, t + 7, tmax, j);
        vstep(t, pl0, tcp, abuf, cbuf, bp, chk, j, sub);
        vstep(t + 1, pl1, tcp, abuf, cbuf, bp, chk, j, sub);
        vstep(t + 2, pl2, tcp, abuf, cbuf, bp, chk, j, sub);
        vstep(t + 3, pl3, tcp, abuf, cbuf, bp, chk, j, sub);
        pl0 = n0; pl1 = n1; pl2 = n2; pl3 = n3;
    }
    for (; t <= tmax; t++) {
        if ((t & 63) == 1) waitchunk(b, (t >> 6) + 1);
        vstep(t, pl0, tcp, abuf, cbuf, bp, chk, j, sub);
        pl0 = pl1; pl1 = pl2; pl2 = pl3;
    }
    __syncthreads();

    const int fslot = (tmax & 1) * 32;
    if (tid < 32) {
        float bv = abuf[fslot + tid];
        int bi = tid;
#pragma unroll
        for (int off = 16; off >= 1; off >>= 1) {
            float ov = __shfl_xor_sync(FULLM, bv, off);
            int oi = __shfl_xor_sync(FULLM, bi, off);
            if (ov > bv || (ov == bv && oi < bi)) { bv = ov; bi = oi; }
        }
        if (tid == 0) {
            sfin[0] = bi;
            if (write_score) out[score_off + b] = bv;
        }
    }
    __syncthreads();
    const int last_tag = sfin[0];

    if (write_pred) {
        const int nA = tmax >> 6;
        if (tid == 0) {
            anch[nA] = cbuf[fslot + last_tag];
            for (int cI = nA; cI >= 1; --cI) anch[cI - 1] = chk[cI * 32 + anch[cI]];
        }
        for (int tt = tmax + tid; tt < Tn; tt += 128)
            out[(size_t)b * Tn + tt] = (float)last_tag;
        __syncthreads();

        if (tid <= nA) {
            int thi = (tid == nA) ? tmax : ((tid + 1) << 6);
            int tg = (tid == nA) ? last_tag : anch[tid + 1];
            for (int tt = thi; tt > (tid << 6); --tt) {
                tg = bp[tt * 32 + tg];
                out[(size_t)b * Tn + tt - 1] = (float)tg;
            }
        }
    }
}

// ================= persistent fused kernel with SM-role isolation ==============
// role codes in g_ctrl[2048+smid]: 0=unclaimed, 1=pending, 2=gemm SM, 3=viterbi SM
__global__ __launch_bounds__(128, 3) void crf_fused(const float* __restrict__ x,
                                                    const int* __restrict__ nwords,
                                                    const float* __restrict__ W,
                                                    const float* __restrict__ trans,
                                                    const float* __restrict__ bias,
                                                    float* __restrict__ out,
                                                    int write_pred, int write_score,
                                                    long long score_off) {
    extern __shared__ char smem[];
    __shared__ int s_role;   // 0=exit, 1=viterbi, 2=gemm worker
    __shared__ int s_batch;
    __shared__ int s_job;

    const int tid = threadIdx.x;
    if (tid == 0) {
        unsigned smid;
        asm("mov.u32 %0, %%smid;" : "=r"(smid));
        int* rp = &g_ctrl[2048 + (smid & 255)];
        int r = atomicCAS(rp, 0, 1);
        if (r == 0) {  // first block on this SM
            int vb = atomicAdd(&g_ctrl[2304], 1);
            if (vb < Bn) {
                s_batch = vb;
                atomicExch(rp, 3);
                s_role = 1;
            } else {
                atomicExch(rp, 2);
                s_role = 2;
            }
        } else {  // co-resident: wait for the winner's decision
            volatile int* vp = rp;
            int v;
            while ((v = *vp) < 2) {}
            s_role = (v == 3) ? 0 : 2;  // exit if this SM hosts viterbi
        }
    }
    __syncthreads();
    const int role = s_role;
    if (role == 0) return;  // leave the viterbi SM uncontended

    if (role == 1) {
        viterbi_role(s_batch, trans, out, write_pred, write_score, score_off,
                     nwords, smem);
        return;
    }
    // gemm worker: pull chunk jobs (c-major -> chunk 0 of all batches first)
    while (true) {
        if (tid == 0) s_job = atomicAdd(&g_ctrl[2305], 1);
        __syncthreads();
        int job = s_job;
        if (job >= NJOBS) break;
        gemm_role(job >> 6, job & 63, x, W, bias, smem);
        __syncthreads();
    }
}

// ---------------- launch ----------------
extern "C" void kernel_launch(void* const* d_in, const int* in_sizes, int n_in,
                              void* d_out, int out_size) {
    const float* x = (const float*)d_in[0];
    const int* nwords = (const int*)d_in[1];
    const float* W = (const float*)d_in[2];
    const float* trans = (const float*)d_in[3];
    const float* bias = (const float*)d_in[4];
    float* out = (float*)d_out;

    const int BT = Bn * Tn;
    int write_pred = 1, write_score = 0;
    long long score_off = BT;
    if (out_size >= BT + Bn) {
        write_score = 1;
    } else if (out_size == Bn) {
        write_pred = 0;
        write_score = 1;
        score_off = 0;
    }

    static int* ctrl_ptr = nullptr;
    if (!ctrl_ptr) cudaGetSymbolAddress((void**)&ctrl_ptr, g_ctrl);

    cudaFuncSetAttribute(crf_fused, cudaFuncAttributeMaxDynamicSharedMemorySize, SMEM_BYTES);

    cudaMemsetAsync(ctrl_ptr, 0, (2048 + 256 + 2) * sizeof(int));
    crf_fused<<<NBLOCKS, 128, SMEM_BYTES>>>(x, nwords, W, trans, bias, out,
                                            write_pred, write_score, score_off);
}